// round 2
// baseline (speedup 1.0000x reference)
#include <cuda_runtime.h>
#include <math.h>

// SparseMoE: T=2048 tokens, D=1024, F=4096, E=8, top-2 routing.
// Pipeline: router (top-2 + softmax gates) -> per-expert token gather ->
// grouped GEMM1 (x @ W1_e, +b1, ReLU) -> grouped GEMM2 (h @ W2_e, +b2, *gate)
// -> combine (sum of the 2 expert outputs per token).

#define D_DIM 1024
#define E_NUM 8
#define F_DIM 4096
#define MAXT  2048
#define MAXROWS (2 * MAXT)

// Scratch (device globals; no cudaMalloc allowed).
__device__ float g_h[(size_t)MAXROWS * F_DIM];   // 67 MB: post-ReLU activations per slot
__device__ float g_y[(size_t)MAXROWS * D_DIM];   // 16.8 MB: gated expert outputs per slot
__device__ int   g_cnt[E_NUM];
__device__ int   g_off[E_NUM];
__device__ int   g_topi[MAXT * 2];
__device__ float g_gate[MAXT * 2];
__device__ int   g_pos[MAXT * 2];
__device__ int   g_slot[MAXT * 2];
__device__ int   g_rowtok[MAXROWS];
__device__ float g_rowgate[MAXROWS];

__global__ void zero_cnt_kernel() {
    if (threadIdx.x < E_NUM) g_cnt[threadIdx.x] = 0;
}

// One warp per token: logits = x_t @ Wn + bn, top-2, softmax over the 2 values.
__global__ void router_kernel(const float* __restrict__ x,
                              const float* __restrict__ Wn,
                              const float* __restrict__ bn, int T) {
    int gw   = (blockIdx.x * blockDim.x + threadIdx.x) >> 5;
    int lane = threadIdx.x & 31;
    if (gw >= T) return;
    const float* xr = x + (size_t)gw * D_DIM;

    float acc[E_NUM];
#pragma unroll
    for (int e = 0; e < E_NUM; e++) acc[e] = 0.f;

    for (int d = lane; d < D_DIM; d += 32) {
        float xv = xr[d];
#pragma unroll
        for (int e = 0; e < E_NUM; e++) acc[e] += xv * Wn[d * E_NUM + e];
    }
#pragma unroll
    for (int off = 16; off; off >>= 1) {
#pragma unroll
        for (int e = 0; e < E_NUM; e++)
            acc[e] += __shfl_xor_sync(0xffffffffu, acc[e], off);
    }

    if (lane == 0) {
        float v[E_NUM];
#pragma unroll
        for (int e = 0; e < E_NUM; e++) v[e] = acc[e] + bn[e];
        // top-1 (strict > : lowest index wins ties, matching jax top_k)
        int i0 = 0;
#pragma unroll
        for (int e = 1; e < E_NUM; e++) if (v[e] > v[i0]) i0 = e;
        int i1 = (i0 == 0) ? 1 : 0;
#pragma unroll
        for (int e = 0; e < E_NUM; e++)
            if (e != i0 && v[e] > v[i1]) i1 = e;

        float ex = expf(v[i1] - v[i0]);     // <= 1
        float g0 = 1.f / (1.f + ex);
        float g1 = ex / (1.f + ex);

        int p0 = atomicAdd(&g_cnt[i0], 1);
        int p1 = atomicAdd(&g_cnt[i1], 1);
        int b = gw * 2;
        g_topi[b]     = i0;  g_topi[b + 1] = i1;
        g_gate[b]     = g0;  g_gate[b + 1] = g1;
        g_pos[b]      = p0;  g_pos[b + 1]  = p1;
    }
}

__global__ void scan_kernel() {
    if (threadIdx.x == 0) {
        int s = 0;
        for (int e = 0; e < E_NUM; e++) { g_off[e] = s; s += g_cnt[e]; }
    }
}

__global__ void build_kernel(int T) {
    int i = blockIdx.x * blockDim.x + threadIdx.x;
    if (i >= T * 2) return;
    int e    = g_topi[i];
    int slot = g_off[e] + g_pos[i];
    g_slot[i]       = slot;
    g_rowtok[slot]  = i >> 1;
    g_rowgate[slot] = g_gate[i];
}

// ---------------- 128x128 tile SGEMM cores (BK=8, 256 thr, 8x8/thread) ----

// GEMM1: h[slot, n] = relu( x[tok(slot), :] @ W1[e][:, n] + b1[e][n] )
__global__ __launch_bounds__(256)
void ffn1_kernel(const float* __restrict__ x,
                 const float* __restrict__ W1,
                 const float* __restrict__ b1) {
    const int e   = blockIdx.z;
    const int cnt = g_cnt[e];
    const int m0  = blockIdx.y * 128;
    if (m0 >= cnt) return;
    const int base = g_off[e];
    const int n0   = blockIdx.x * 128;
    const int tid  = threadIdx.x;

    __shared__ float As[8][128];
    __shared__ float Bs[8][128];

    // A load assignment: 2 threads per row, float4 each
    const int arow = tid >> 1;
    const int ak   = (tid & 1) * 4;
    int gm   = m0 + arow;
    int asrc = base + ((gm < cnt) ? gm : (cnt - 1));
    const float* aptr = x + (size_t)g_rowtok[asrc] * D_DIM + ak;

    // B load assignment: 32 threads per row (128 floats), float4 each
    const int brow = tid >> 5;
    const int bcol = (tid & 31) * 4;
    const float* bptr = W1 + (size_t)e * D_DIM * F_DIM + (size_t)brow * F_DIM + n0 + bcol;

    const int rm = (tid >> 4) * 4;   // rows {rm..rm+3, rm+64..rm+67}
    const int cn = (tid & 15) * 4;   // cols {cn..cn+3, cn+64..cn+67}

    float acc[8][8];
#pragma unroll
    for (int i = 0; i < 8; i++)
#pragma unroll
        for (int j = 0; j < 8; j++) acc[i][j] = 0.f;

    for (int k0 = 0; k0 < D_DIM; k0 += 8) {
        float4 av = *(const float4*)(aptr + k0);
        float4 bv = *(const float4*)(bptr);
        bptr += 8 * F_DIM;
        __syncthreads();
        As[ak + 0][arow] = av.x; As[ak + 1][arow] = av.y;
        As[ak + 2][arow] = av.z; As[ak + 3][arow] = av.w;
        *(float4*)&Bs[brow][bcol] = bv;
        __syncthreads();
#pragma unroll
        for (int kk = 0; kk < 8; kk++) {
            float a[8], b[8];
            *(float4*)&a[0] = *(const float4*)&As[kk][rm];
            *(float4*)&a[4] = *(const float4*)&As[kk][rm + 64];
            *(float4*)&b[0] = *(const float4*)&Bs[kk][cn];
            *(float4*)&b[4] = *(const float4*)&Bs[kk][cn + 64];
#pragma unroll
            for (int i = 0; i < 8; i++)
#pragma unroll
                for (int j = 0; j < 8; j++) acc[i][j] += a[i] * b[j];
        }
    }

#pragma unroll
    for (int i = 0; i < 8; i++) {
        int r   = (i < 4) ? (rm + i) : (rm + 60 + i);
        int gmr = m0 + r;
        if (gmr >= cnt) continue;
        size_t orow = (size_t)(base + gmr) * F_DIM + n0;
#pragma unroll
        for (int j = 0; j < 8; j++) {
            int c = (j < 4) ? (cn + j) : (cn + 60 + j);
            float hv = acc[i][j] + b1[e * F_DIM + n0 + c];
            g_h[orow + c] = hv > 0.f ? hv : 0.f;
        }
    }
}

// GEMM2: y[slot, n] = gate(slot) * ( h[slot, :] @ W2[e][:, n] + b2[e][n] )
__global__ __launch_bounds__(256)
void ffn2_kernel(const float* __restrict__ W2,
                 const float* __restrict__ b2) {
    const int e   = blockIdx.z;
    const int cnt = g_cnt[e];
    const int m0  = blockIdx.y * 128;
    if (m0 >= cnt) return;
    const int base = g_off[e];
    const int n0   = blockIdx.x * 128;
    const int tid  = threadIdx.x;

    __shared__ float As[8][128];
    __shared__ float Bs[8][128];

    const int arow = tid >> 1;
    const int ak   = (tid & 1) * 4;
    int gm  = m0 + arow;
    int row = base + ((gm < cnt) ? gm : (cnt - 1));
    const float* aptr = g_h + (size_t)row * F_DIM + ak;

    const int brow = tid >> 5;
    const int bcol = (tid & 31) * 4;
    const float* bptr = W2 + (size_t)e * F_DIM * D_DIM + (size_t)brow * D_DIM + n0 + bcol;

    const int rm = (tid >> 4) * 4;
    const int cn = (tid & 15) * 4;

    float acc[8][8];
#pragma unroll
    for (int i = 0; i < 8; i++)
#pragma unroll
        for (int j = 0; j < 8; j++) acc[i][j] = 0.f;

    for (int k0 = 0; k0 < F_DIM; k0 += 8) {
        float4 av = *(const float4*)(aptr + k0);
        float4 bv = *(const float4*)(bptr);
        bptr += 8 * D_DIM;
        __syncthreads();
        As[ak + 0][arow] = av.x; As[ak + 1][arow] = av.y;
        As[ak + 2][arow] = av.z; As[ak + 3][arow] = av.w;
        *(float4*)&Bs[brow][bcol] = bv;
        __syncthreads();
#pragma unroll
        for (int kk = 0; kk < 8; kk++) {
            float a[8], b[8];
            *(float4*)&a[0] = *(const float4*)&As[kk][rm];
            *(float4*)&a[4] = *(const float4*)&As[kk][rm + 64];
            *(float4*)&b[0] = *(const float4*)&Bs[kk][cn];
            *(float4*)&b[4] = *(const float4*)&Bs[kk][cn + 64];
#pragma unroll
            for (int i = 0; i < 8; i++)
#pragma unroll
                for (int j = 0; j < 8; j++) acc[i][j] += a[i] * b[j];
        }
    }

#pragma unroll
    for (int i = 0; i < 8; i++) {
        int r   = (i < 4) ? (rm + i) : (rm + 60 + i);
        int gmr = m0 + r;
        if (gmr >= cnt) continue;
        float gate  = g_rowgate[base + gmr];
        size_t orow = (size_t)(base + gmr) * D_DIM + n0;
#pragma unroll
        for (int j = 0; j < 8; j++) {
            int c = (j < 4) ? (cn + j) : (cn + 60 + j);
            g_y[orow + c] = gate * (acc[i][j] + b2[e * D_DIM + n0 + c]);
        }
    }
}

__global__ void combine_kernel(float* __restrict__ out, int T) {
    int i = blockIdx.x * blockDim.x + threadIdx.x;
    if (i >= T * D_DIM) return;
    int t = i >> 10;           // / D_DIM
    int d = i & (D_DIM - 1);   // % D_DIM
    out[i] = g_y[(size_t)g_slot[t * 2] * D_DIM + d] +
             g_y[(size_t)g_slot[t * 2 + 1] * D_DIM + d];
}

extern "C" void kernel_launch(void* const* d_in, const int* in_sizes, int n_in,
                              void* d_out, int out_size) {
    const float* x  = (const float*)d_in[0];
    const float* Wn = (const float*)d_in[1];
    const float* bn = (const float*)d_in[2];
    const float* W1 = (const float*)d_in[3];
    const float* b1 = (const float*)d_in[4];
    const float* W2 = (const float*)d_in[5];
    const float* b2 = (const float*)d_in[6];
    const int T = in_sizes[0] / D_DIM;

    zero_cnt_kernel<<<1, 32>>>();
    router_kernel<<<(T * 32 + 255) / 256, 256>>>(x, Wn, bn, T);
    scan_kernel<<<1, 32>>>();
    build_kernel<<<(T * 2 + 255) / 256, 256>>>(T);

    const int MT = (T + 127) / 128;   // worst case: one expert gets all tokens
    dim3 g1(F_DIM / 128, MT, E_NUM);
    ffn1_kernel<<<g1, 256>>>(x, W1, b1);
    dim3 g2(D_DIM / 128, MT, E_NUM);
    ffn2_kernel<<<g2, 256>>>(W2, b2);

    combine_kernel<<<(T * D_DIM + 255) / 256, 256>>>((float*)d_out, T);
}